// round 9
// baseline (speedup 1.0000x reference)
#include <cuda_runtime.h>

// LengthRegulator, fused single kernel with warp-level scan prologue:
// warp 0 scans the batch's 512 durations (16/lane serial + shfl prefix) and
// scatters this block's 64-frame frame->token window; then all 12 warps run
// the dense gather + streaming-store copy. One barrier total.

#define BB 32
#define SS 512
#define DD 384
#define T_OUT 2048
#define DV (DD / 4)     // 96 float4 per row
#define FRB 64          // frames per block
#define NT 384          // threads per block (12 warps, all SMSPs)
#define FL 4            // frame lanes (NT / DV)

__global__ __launch_bounds__(NT)
void lr_fused_kernel(const float4* __restrict__ x4,
                     const int* __restrict__ dur,
                     float4* __restrict__ out4) {
    __shared__ int sidx[FRB];          // frame -> token for this window

    const int b   = blockIdx.y;
    const int t0  = blockIdx.x * FRB;
    const int tid = threadIdx.x;

    // ── prologue: warp 0 only ───────────────────────────────────────────
    if (tid < 32) {
        // lane owns tokens [tid*16, tid*16+16): 4 x int4 loads (L2-resident)
        const int4* dp = (const int4*)(dur + b * SS) + tid * 4;
        int4 q0 = __ldg(&dp[0]);
        int4 q1 = __ldg(&dp[1]);
        int4 q2 = __ldg(&dp[2]);
        int4 q3 = __ldg(&dp[3]);
        int d[16] = {q0.x, q0.y, q0.z, q0.w, q1.x, q1.y, q1.z, q1.w,
                     q2.x, q2.y, q2.z, q2.w, q3.x, q3.y, q3.z, q3.w};

        int sum = 0;
        #pragma unroll
        for (int i = 0; i < 16; ++i) sum += d[i];

        // exclusive warp prefix of per-lane sums
        int pref = sum;
        #pragma unroll
        for (int off = 1; off < 32; off <<= 1) {
            int v = __shfl_up_sync(0xFFFFFFFFu, pref, off);
            if (tid >= off) pref += v;
        }
        int start = pref - sum;        // exclusive start of this lane's tokens

        // scatter clipped intervals into the window
        #pragma unroll
        for (int i = 0; i < 16; ++i) {
            const int e  = start + d[i];
            int lo = start > t0 ? start : t0;
            int hi = e < t0 + FRB ? e : t0 + FRB;
            for (int k = lo; k < hi; ++k)
                sidx[k - t0] = tid * 16 + i;
            start = e;
        }
    }
    __syncthreads();

    // ── copy: c = channel (0..95 float4), f = frame lane (0..3) ─────────
    const int c = tid % DV;            // contiguous within warp
    const int f = tid / DV;
    const float4* __restrict__ xb = x4 + (size_t)b * SS * DV + c;
    float4* __restrict__ ob = out4 + ((size_t)b * T_OUT + t0) * DV + c;

    #pragma unroll
    for (int g = 0; g < FRB / FL; g += 4) {
        int tk[4];
        #pragma unroll
        for (int i = 0; i < 4; ++i)
            tk[i] = sidx[f + FL * (g + i)];

        float4 v[4];
        #pragma unroll
        for (int i = 0; i < 4; ++i)
            v[i] = __ldg(&xb[(size_t)tk[i] * DV]);

        #pragma unroll
        for (int i = 0; i < 4; ++i)
            __stcs(&ob[(size_t)(f + FL * (g + i)) * DV], v[i]);
    }
}

extern "C" void kernel_launch(void* const* d_in, const int* in_sizes, int n_in,
                              void* d_out, int out_size) {
    const float4* x4  = (const float4*)d_in[0];   // x [B,S,D] f32
    const int*    dur = (const int*)d_in[1];      // durations [B,S] i32
    float4* out4 = (float4*)d_out;                // [B,T_OUT,D] f32

    lr_fused_kernel<<<dim3(T_OUT / FRB, BB), NT>>>(x4, dur, out4);
}